// round 12
// baseline (speedup 1.0000x reference)
#include <cuda_runtime.h>
#include <math.h>

#define Bn 32
#define Tn 512
#define Hn 2048
#define Kn 128

// Scratch (no allocations allowed)
__device__ float g_logits[Bn * Tn * Kn];   // 8 MB
__device__ float g_llh[Bn];

// ---------------------------------------------------------------------------
// GEMM: logits[m][n] = sum_h hiddens[m][h] * W[h][n] + b[n]   (R1 config)
// BM=64, BN=128, BK=16, 256 threads, 8x4 per-thread tile.
// ---------------------------------------------------------------------------
__global__ __launch_bounds__(256) void gemm_kernel(
    const float* __restrict__ hid, const float* __restrict__ W,
    const float* __restrict__ bias)
{
    __shared__ float As[16][64];
    __shared__ float Bs[16][128];

    const int tid = threadIdx.x;
    const int m0  = blockIdx.x * 64;
    const int ty  = tid >> 5;
    const int tx  = tid & 31;

    float acc[8][4];
#pragma unroll
    for (int i = 0; i < 8; i++)
#pragma unroll
        for (int jj = 0; jj < 4; jj++) acc[i][jj] = 0.f;

    const int arow = tid >> 2;
    const int ac4  = (tid & 3) * 4;

    for (int k0 = 0; k0 < Hn; k0 += 16) {
        float4 a4 = *(const float4*)(hid + (size_t)(m0 + arow) * Hn + k0 + ac4);
        As[ac4 + 0][arow] = a4.x;
        As[ac4 + 1][arow] = a4.y;
        As[ac4 + 2][arow] = a4.z;
        As[ac4 + 3][arow] = a4.w;
        {
            int idx = tid;
            int r = idx >> 5, c = (idx & 31) * 4;
            *(float4*)(&Bs[r][c]) = *(const float4*)(W + (size_t)(k0 + r) * Kn + c);
            idx = tid + 256;
            r = idx >> 5; c = (idx & 31) * 4;
            *(float4*)(&Bs[r][c]) = *(const float4*)(W + (size_t)(k0 + r) * Kn + c);
        }
        __syncthreads();

#pragma unroll
        for (int k = 0; k < 16; k++) {
            float4 b4 = *(const float4*)(&Bs[k][tx * 4]);
            float a[8];
#pragma unroll
            for (int i = 0; i < 8; i++) a[i] = As[k][ty * 8 + i];
#pragma unroll
            for (int i = 0; i < 8; i++) {
                acc[i][0] += a[i] * b4.x;
                acc[i][1] += a[i] * b4.y;
                acc[i][2] += a[i] * b4.z;
                acc[i][3] += a[i] * b4.w;
            }
        }
        __syncthreads();
    }

    const int n0 = tx * 4;
    float4 bb = *(const float4*)(bias + n0);
#pragma unroll
    for (int i = 0; i < 8; i++) {
        int row = m0 + ty * 8 + i;
        float4 o;
        o.x = acc[i][0] + bb.x;
        o.y = acc[i][1] + bb.y;
        o.z = acc[i][2] + bb.z;
        o.w = acc[i][3] + bb.w;
        *(float4*)(g_logits + (size_t)row * Kn + n0) = o;
    }
}

// ---------------------------------------------------------------------------
// CRF recurrences. 64 blocks x 256 threads.
// blocks [0,32): forward logsumexp (lagged shift, 1 barrier/step)
// blocks [32,64): viterbi, TREE-structured argmax (no 64-deep select chain),
//                 1 barrier/step, smem backpointers + in-block backtrace.
// j = tid>>1 (tag), h = tid&1 (source half).
// Viterbi smem layout:
//   [0,1024)        sh_s[2][128] double-buffered scores
//   [1024,1536)     sfin[128]
//   [1536,69120)    Tt[128][132]  (Tt[j*132+i] = trans[i*128+j])
//   [69120,134528)  bp[511*128] bytes
// ---------------------------------------------------------------------------
#define TT_PITCH 132
#define SMEM_BYTES (69120 + (Tn - 1) * Kn)

__global__ __launch_bounds__(256) void crf_kernel(
    const int* __restrict__ mask, const int* __restrict__ labels,
    const float* __restrict__ startT, const float* __restrict__ endT,
    const float* __restrict__ trans, float* __restrict__ out)
{
    extern __shared__ char smem[];
    const int tid = threadIdx.x;
    const int j = tid >> 1, h = tid & 1;
    const unsigned FULL = 0xFFFFFFFFu;
    const int bidx = blockIdx.x;

    if (bidx < Bn) {
        // ================= FORWARD =================
        float* p2    = (float*)smem;                 // [2][128]
        float* sC    = (float*)(smem + 1024);
        float* sa0   = (float*)(smem + 1032);
        float* shred = (float*)(smem + 1056);
        int*   shredi= (int*)(smem + 1088);

        const int b = bidx;
        float Eh[64];
#pragma unroll
        for (int i = 0; i < 64; i++)
            Eh[i] = __expf(trans[(h * 64 + i) * Kn + j]);

        const float* lg = g_logits + (size_t)b * Tn * Kn;
        float alpha = startT[j] + lg[j];
        float C0 = startT[0] + lg[0];
        if (h == 0) p2[j] = __expf(alpha - C0);
        if (tid == 0) { sC[0] = C0; sa0[0] = alpha; }
        float e_next = lg[Kn + j];
        int mt_next = mask[b * Tn + 1];
        __syncthreads();

        for (int t = 1; t < Tn; t++) {
            const int cur = (t - 1) & 1, nb = t & 1;
            float Cu = sC[cur];
            float A0 = sa0[cur];
            float emit = e_next;
            int mt = mt_next;
            if (t + 1 < Tn) {
                e_next = lg[(size_t)(t + 1) * Kn + j];
                mt_next = mask[b * Tn + t + 1];
            }

            const float4* p4 = (const float4*)(p2 + cur * Kn + h * 64);
            float s0 = 0.f, s1 = 0.f, s2 = 0.f, s3 = 0.f;
#pragma unroll
            for (int g = 0; g < 4; g++) {
                float4 va = p4[4 * g + 0];
                float4 vb = p4[4 * g + 1];
                float4 vc = p4[4 * g + 2];
                float4 vd = p4[4 * g + 3];
                s0 += va.x * Eh[16 * g + 0];  s0 += va.y * Eh[16 * g + 1];
                s0 += va.z * Eh[16 * g + 2];  s0 += va.w * Eh[16 * g + 3];
                s1 += vb.x * Eh[16 * g + 4];  s1 += vb.y * Eh[16 * g + 5];
                s1 += vb.z * Eh[16 * g + 6];  s1 += vb.w * Eh[16 * g + 7];
                s2 += vc.x * Eh[16 * g + 8];  s2 += vc.y * Eh[16 * g + 9];
                s2 += vc.z * Eh[16 * g + 10]; s2 += vc.w * Eh[16 * g + 11];
                s3 += vd.x * Eh[16 * g + 12]; s3 += vd.y * Eh[16 * g + 13];
                s3 += vd.z * Eh[16 * g + 14]; s3 += vd.w * Eh[16 * g + 15];
            }
            float s = (s0 + s1) + (s2 + s3);
            s += __shfl_xor_sync(FULL, s, 1);

            float nxt = Cu + __logf(s) + emit;
            alpha = (mt > 0) ? nxt : alpha;

            if (h == 0) p2[nb * Kn + j] = __expf(alpha - A0);
            if (tid == 0) { sC[nb] = A0; sa0[nb] = alpha; }
            __syncthreads();
        }

        // logZ (exact reduce)
        float v = alpha + endT[j];
        float wm = v;
#pragma unroll
        for (int o = 16; o; o >>= 1)
            wm = fmaxf(wm, __shfl_xor_sync(FULL, wm, o));
        if ((tid & 31) == 0) shred[tid >> 5] = wm;
        __syncthreads();
        float m = shred[0];
#pragma unroll
        for (int w = 1; w < 8; w++) m = fmaxf(m, shred[w]);
        __syncthreads();
        float pc = (h == 0) ? __expf(v - m) : 0.f;
#pragma unroll
        for (int o = 16; o; o >>= 1)
            pc += __shfl_xor_sync(FULL, pc, o);
        if ((tid & 31) == 0) shred[tid >> 5] = pc;
        __syncthreads();
        float Z = 0.f;
#pragma unroll
        for (int w = 0; w < 8; w++) Z += shred[w];
        float logZ = m + __logf(Z);
        __syncthreads();

        // path score
        float sc = 0.f;
        int msum = 0;
        for (int t = tid; t < Tn; t += 256) {
            msum += mask[b * Tn + t];
            if (t >= 1) {
                int cur  = labels[b * Tn + t];
                int prev = labels[b * Tn + t - 1];
                float mf = (float)mask[b * Tn + t];
                sc += (trans[prev * Kn + cur] + lg[(size_t)t * Kn + cur]) * mf;
            }
        }
#pragma unroll
        for (int o = 16; o; o >>= 1) {
            sc   += __shfl_xor_sync(FULL, sc, o);
            msum += __shfl_xor_sync(FULL, msum, o);
        }
        if ((tid & 31) == 0) { shred[tid >> 5] = sc; shredi[tid >> 5] = msum; }
        __syncthreads();
        if (tid == 0) {
            float S = 0.f; int Mc = 0;
#pragma unroll
            for (int w = 0; w < 8; w++) { S += shred[w]; Mc += shredi[w]; }
            int l0 = labels[b * Tn];
            S += startT[l0] + lg[l0];
            int last = labels[b * Tn + (Mc - 1)];
            S += endT[last];
            g_llh[b] = S - logZ;
        }
    } else {
        // ================= VITERBI (tree argmax) =================
        float* sh_s = (float*)smem;                  // [2][128]
        float* sfin = (float*)(smem + 1024);
        float* Tt   = (float*)(smem + 1536);
        unsigned char* bp = (unsigned char*)(smem + 69120);

        const int b = bidx - Bn;
        float Th[64];
#pragma unroll
        for (int i = 0; i < 64; i++)
            Th[i] = trans[(h * 64 + i) * Kn + j];

        // transposed trans tile: Tt[jj*132 + i] = trans[i*128 + jj]
        for (int idx = tid; idx < Kn * Kn; idx += 256) {
            int i = idx >> 7, jj = idx & 127;
            Tt[jj * TT_PITCH + i] = trans[idx];
        }

        const float* lg = g_logits + (size_t)b * Tn * Kn;
        float sj = startT[j] + lg[j];
        if (h == 0) sh_s[j] = sj;
        float e_next = lg[Kn + j];
        int mt_next = mask[b * Tn + 1];
        __syncthreads();

        for (int t = 1; t < Tn; t++) {
            const int cur = (t - 1) & 1, nb = t & 1;
            float emit = e_next;
            int mt = mt_next;
            if (t + 1 < Tn) {
                e_next = lg[(size_t)(t + 1) * Kn + j];
                mt_next = mask[b * Tn + t + 1];
            }

            // ---- pass 1: group maxima via FMNMX trees (no select chain) ----
            const float4* s4 = (const float4*)(sh_s + cur * Kn + h * 64);
            float gm[8];
#pragma unroll
            for (int g = 0; g < 8; g++) {
                float4 va = s4[2 * g];
                float4 vb = s4[2 * g + 1];
                float c0 = va.x + Th[8 * g + 0];
                float c1 = va.y + Th[8 * g + 1];
                float c2 = va.z + Th[8 * g + 2];
                float c3 = va.w + Th[8 * g + 3];
                float c4 = vb.x + Th[8 * g + 4];
                float c5 = vb.y + Th[8 * g + 5];
                float c6 = vb.z + Th[8 * g + 6];
                float c7 = vb.w + Th[8 * g + 7];
                gm[g] = fmaxf(fmaxf(fmaxf(c0, c1), fmaxf(c2, c3)),
                              fmaxf(fmaxf(c4, c5), fmaxf(c6, c7)));
            }
            float best = fmaxf(fmaxf(fmaxf(gm[0], gm[1]), fmaxf(gm[2], gm[3])),
                               fmaxf(fmaxf(gm[4], gm[5]), fmaxf(gm[6], gm[7])));
            // first group attaining best (integer-min tree)
            int g0 = (gm[0] == best) ? 0 : 8;
            int g1 = (gm[1] == best) ? 1 : 8;
            int g2 = (gm[2] == best) ? 2 : 8;
            int g3 = (gm[3] == best) ? 3 : 8;
            int g4 = (gm[4] == best) ? 4 : 8;
            int g5 = (gm[5] == best) ? 5 : 8;
            int g6 = (gm[6] == best) ? 6 : 8;
            int g7 = (gm[7] == best) ? 7 : 8;
            int bg = min(min(min(g0, g1), min(g2, g3)),
                         min(min(g4, g5), min(g6, g7)));

            // ---- pass 2: exact first-index within winning group (smem) ----
            const int base = h * 64 + bg * 8;
            const float4* pv = (const float4*)(sh_s + cur * Kn + base);
            float4 u0 = pv[0], u1 = pv[1];
            const float4* tv = (const float4*)(Tt + j * TT_PITCH + base);
            float4 w0 = tv[0], w1 = tv[1];
            float d0 = u0.x + w0.x, d1 = u0.y + w0.y;
            float d2 = u0.z + w0.z, d3 = u0.w + w0.w;
            float d4 = u1.x + w1.x, d5 = u1.y + w1.y;
            float d6 = u1.z + w1.z, d7 = u1.w + w1.w;
            int q0 = (d0 == best) ? 0 : 8;
            int q1 = (d1 == best) ? 1 : 8;
            int q2 = (d2 == best) ? 2 : 8;
            int q3 = (d3 == best) ? 3 : 8;
            int q4 = (d4 == best) ? 4 : 8;
            int q5 = (d5 == best) ? 5 : 8;
            int q6 = (d6 == best) ? 6 : 8;
            int q7 = (d7 == best) ? 7 : 8;
            int aq = min(min(min(q0, q1), min(q2, q3)),
                         min(min(q4, q5), min(q6, q7)));
            int ai = base + aq;

            // cross-h combine; h==0 wins ties (lower global index)
            float ob = __shfl_xor_sync(FULL, best, 1);
            int   oi = __shfl_xor_sync(FULL, ai, 1);
            float lb = (h == 0) ? best : ob;
            int   li = (h == 0) ? ai   : oi;
            float hb = (h == 0) ? ob   : best;
            int   hi = (h == 0) ? oi   : ai;
            float fb; int fa;
            if (hb > lb) { fb = hb; fa = hi; } else { fb = lb; fa = li; }

            float ns; int bpv;
            if (mt > 0) { ns = fb + emit; bpv = fa; }
            else        { ns = sj;        bpv = j;  }
            sj = ns;
            if (h == 0) {
                sh_s[nb * Kn + j] = sj;
                bp[(size_t)(t - 1) * Kn + j] = (unsigned char)bpv;
            }
            __syncthreads();
        }

        if (h == 0) sfin[j] = sj + endT[j];
        __syncthreads();
        if (tid == 0) {
            float bbest = sfin[0];
            int btag = 0;
            for (int q = 1; q < Kn; q++) {
                float vv = sfin[q];
                if (vv > bbest) { bbest = vv; btag = q; }
            }
            int tag = btag;
            out[b * Tn + (Tn - 1)] = (float)tag;
            for (int t = Tn - 2; t >= 0; t--) {
                tag = bp[(size_t)t * Kn + tag];
                out[b * Tn + t] = (float)tag;
            }
        }
    }
}

// ---------------------------------------------------------------------------
// loss = -mean(llh)
// ---------------------------------------------------------------------------
__global__ void loss_kernel(float* __restrict__ out)
{
    const unsigned FULL = 0xFFFFFFFFu;
    float v = (threadIdx.x < Bn) ? g_llh[threadIdx.x] : 0.f;
#pragma unroll
    for (int o = 16; o; o >>= 1) v += __shfl_xor_sync(FULL, v, o);
    if (threadIdx.x == 0) out[Bn * Tn] = -(v / (float)Bn);
}

extern "C" void kernel_launch(void* const* d_in, const int* in_sizes, int n_in,
                              void* d_out, int out_size)
{
    const float* hiddens = (const float*)d_in[0];
    const int*   mask    = (const int*)d_in[1];
    const int*   labels  = (const int*)d_in[2];
    const float* W       = (const float*)d_in[3];
    const float* bias    = (const float*)d_in[4];
    const float* startT  = (const float*)d_in[5];
    const float* endT    = (const float*)d_in[6];
    const float* trans   = (const float*)d_in[7];
    float* out = (float*)d_out;

    gemm_kernel<<<(Bn * Tn) / 64, 256>>>(hiddens, W, bias);

    cudaFuncSetAttribute(crf_kernel, cudaFuncAttributeMaxDynamicSharedMemorySize,
                         SMEM_BYTES);
    crf_kernel<<<2 * Bn, 256, SMEM_BYTES>>>(mask, labels, startT, endT, trans, out);

    loss_kernel<<<1, 32>>>(out);
}